// round 11
// baseline (speedup 1.0000x reference)
#include <cuda_runtime.h>

#define NT   128    // B*T
#define BB   16
#define TT   8
#define CC   512
#define C8   64
#define HW4  196    // 784/4
#define NQ   4      // phase quarters (4 batches each)
#define SL_Q 4096   // slices (blocks) per quarter

// Scratch (no device allocation -> __device__ globals)
__device__ float g_xv[NT * CC];
__device__ float g_left[NT * C8];
__device__ float g_right[NT * C8];
__device__ float g_state[NT * C8];

// ---------------------------------------------------------------------------
// Kernel 1: spatial mean pool for one quarter. 4 rows/block, 64 thr/row.
// ---------------------------------------------------------------------------
__global__ void pool_k(const float* __restrict__ x, int slice0) {
    __shared__ float s_part[4][2];
    int tid = threadIdx.x;
    int sub = tid >> 6, i = tid & 63;
    int row = (slice0 + blockIdx.x) * 4 + sub;
    const float4* xi = reinterpret_cast<const float4*>(x) + (size_t)row * HW4;

    float4 v0 = xi[i];
    float4 v1 = xi[i + 64];
    float4 v2 = xi[i + 128];
    float s = 0.f;
    if (i < 4) { float4 tv = xi[i + 192]; s = (tv.x + tv.y) + (tv.z + tv.w); }
    s += (v0.x + v0.y) + (v0.z + v0.w);
    s += (v1.x + v1.y) + (v1.z + v1.w);
    s += (v2.x + v2.y) + (v2.z + v2.w);

    #pragma unroll
    for (int o = 16; o; o >>= 1) s += __shfl_xor_sync(0xffffffffu, s, o);
    if ((i & 31) == 0) s_part[sub][i >> 5] = s;
    __syncthreads();
    if (i == 0)
        g_xv[row] = (s_part[sub][0] + s_part[sub][1]) * (1.0f / 784.0f);
}

// ---------------------------------------------------------------------------
// Kernel 2: gemm + BN + ReLU for one quarter (32 nts, 32 blocks). Proven body.
// ---------------------------------------------------------------------------
__global__ void gemm_bn_k(const float* __restrict__ w1,
                          const float* __restrict__ bn1g, const float* __restrict__ bn1b,
                          const float* __restrict__ bn1m, const float* __restrict__ bn1v,
                          const float* __restrict__ w2,
                          const float* __restrict__ bn2g, const float* __restrict__ bn2b,
                          const float* __restrict__ bn2m, const float* __restrict__ bn2v,
                          int nt0) {
    __shared__ float sx[CC];
    int nt  = nt0 + blockIdx.x;
    int tid = threadIdx.x;
    #pragma unroll
    for (int i = tid; i < CC; i += 128) sx[i] = g_xv[nt * CC + i];
    __syncthreads();

    int ch = tid & 63;
    const float* wsel = (tid < 64) ? w1   : w2;
    const float* gsel = (tid < 64) ? bn1g : bn2g;
    const float* bsel = (tid < 64) ? bn1b : bn2b;
    const float* msel = (tid < 64) ? bn1m : bn2m;
    const float* vsel = (tid < 64) ? bn1v : bn2v;

    const float4* wr4 = reinterpret_cast<const float4*>(wsel + ch * CC);
    const float4* sx4 = reinterpret_cast<const float4*>(sx);
    float a0 = 0.f, a1 = 0.f, a2 = 0.f, a3 = 0.f;
    #pragma unroll 8
    for (int k = 0; k < CC / 4; k++) {
        float4 wv = __ldg(wr4 + k);
        float4 xv = sx4[k];
        a0 += xv.x * wv.x;
        a1 += xv.y * wv.y;
        a2 += xv.z * wv.z;
        a3 += xv.w * wv.w;
    }
    float acc   = (a0 + a1) + (a2 + a3);
    float scale = gsel[ch] * rsqrtf(vsel[ch] + 1e-5f);
    float val   = fmaxf((acc - msel[ch]) * scale + bsel[ch], 0.f);
    if (tid < 64) g_left[nt * C8 + ch]  = val;
    else          g_right[nt * C8 + ch] = val;
}

// ---------------------------------------------------------------------------
// Kernel 3: register-resident gated scan for one quarter (4 warps = 4 batches).
// ---------------------------------------------------------------------------
__global__ void scan_rec_k(const float* __restrict__ gamma_w,
                           const float* __restrict__ gamma_b, int b0) {
    int b    = b0 + (threadIdx.x >> 5);
    int lane = threadIdx.x & 31;

    float L0[7], L1[7], R0[7], R1[7];
    #pragma unroll
    for (int t = 0; t < 7; t++) {
        L0[t] = g_left [(b * TT + t)     * C8 + lane];
        L1[t] = g_left [(b * TT + t)     * C8 + lane + 32];
        R0[t] = g_right[(b * TT + t + 1) * C8 + lane];
        R1[t] = g_right[(b * TT + t + 1) * C8 + lane + 32];
    }
    float gm0 = __ldg(gamma_w + lane);
    float gm1 = __ldg(gamma_w + lane + 32);
    float gm2 = __ldg(gamma_w + lane + 64);
    float gm3 = __ldg(gamma_w + lane + 96);
    float gb  = __ldg(gamma_b);

    float s0 = 1.f, s1 = 1.f;
    #pragma unroll
    for (int t = 0; t < TT; t++) {
        float d0 = (t < TT - 1) ? (L0[t] - R0[t]) : 1.f;
        float d1 = (t < TT - 1) ? (L1[t] - R1[t]) : 1.f;
        float acc = d0 * gm0 + d1 * gm1 + s0 * gm2 + s1 * gm3;
        #pragma unroll
        for (int o = 16; o; o >>= 1) acc += __shfl_xor_sync(0xffffffffu, acc, o);
        float g = 1.0f / (1.0f + __expf(-(acc + gb)));
        s0 = d0 * g + s0 * (1.0f - g);
        s1 = d1 * g + s1 * (1.0f - g);
        g_state[(b * TT + t) * C8 + lane]      = s0;
        g_state[(b * TT + t) * C8 + lane + 32] = s1;
    }
}

// ---------------------------------------------------------------------------
// Kernel 4: fused attention + scale for one quarter. Runs right after its
// quarter's pool -> x[q] (51 MB) is fully L2-resident -> near-zero DRAM reads.
// ---------------------------------------------------------------------------
__global__ void scale_att_k(const float* __restrict__ x,
                            const float* __restrict__ Wa_w,
                            const float* __restrict__ Wa_b,
                            float* __restrict__ out, int slice0) {
    __shared__ float s_part[4][2];
    int tid  = threadIdx.x;
    int sub  = tid >> 6, i = tid & 63;
    int row  = (slice0 + blockIdx.x) * 4 + sub;   // (nt*CC + c) row id
    int nt   = row >> 9;
    int c    = row & (CC - 1);

    const float4* xi = reinterpret_cast<const float4*>(x)   + (size_t)row * HW4;
    float4*       xo = reinterpret_cast<float4*>(out)       + (size_t)row * HW4;

    float4 v0 = __ldg(xi + i);
    float4 v1 = __ldg(xi + i + 64);
    float4 v2 = __ldg(xi + i + 128);
    float4 v3;
    bool tail = (i < 4);
    if (tail) v3 = __ldg(xi + i + 192);

    float p = g_state[nt * C8 + i] * __ldg(Wa_w + c * C8 + i);
    #pragma unroll
    for (int o = 16; o; o >>= 1) p += __shfl_xor_sync(0xffffffffu, p, o);
    if ((i & 31) == 0) s_part[sub][i >> 5] = p;
    __syncthreads();
    float a = s_part[sub][0] + s_part[sub][1] + __ldg(Wa_b + c);
    float s = 1.0f / (1.0f + __expf(-a));

    v0.x *= s; v0.y *= s; v0.z *= s; v0.w *= s;
    v1.x *= s; v1.y *= s; v1.z *= s; v1.w *= s;
    v2.x *= s; v2.y *= s; v2.z *= s; v2.w *= s;
    __stcs(xo + i,       v0);
    __stcs(xo + i + 64,  v1);
    __stcs(xo + i + 128, v2);
    if (tail) {
        v3.x *= s; v3.y *= s; v3.z *= s; v3.w *= s;
        __stcs(xo + i + 192, v3);
    }
}

// ---------------------------------------------------------------------------
// Quarter-phased serial chain: pool(q) -> gemm(q) -> scan(q) -> scale(q).
// scale(q) re-reads x[q] while it is still L2-resident from pool(q).
// ---------------------------------------------------------------------------
extern "C" void kernel_launch(void* const* d_in, const int* in_sizes, int n_in,
                              void* d_out, int out_size) {
    const float* x       = (const float*)d_in[0];
    const float* w1      = (const float*)d_in[1];
    const float* bn1_g   = (const float*)d_in[2];
    const float* bn1_b   = (const float*)d_in[3];
    const float* bn1_m   = (const float*)d_in[4];
    const float* bn1_v   = (const float*)d_in[5];
    const float* w2      = (const float*)d_in[6];
    const float* bn2_g   = (const float*)d_in[7];
    const float* bn2_b   = (const float*)d_in[8];
    const float* bn2_m   = (const float*)d_in[9];
    const float* bn2_v   = (const float*)d_in[10];
    const float* Wa_w    = (const float*)d_in[11];
    const float* Wa_b    = (const float*)d_in[12];
    const float* gamma_w = (const float*)d_in[13];
    const float* gamma_b = (const float*)d_in[14];
    float* out = (float*)d_out;

    for (int q = 0; q < NQ; q++) {
        pool_k<<<SL_Q, 256>>>(x, q * SL_Q);
        gemm_bn_k<<<NT / NQ, 128>>>(w1, bn1_g, bn1_b, bn1_m, bn1_v,
                                    w2, bn2_g, bn2_b, bn2_m, bn2_v,
                                    q * (NT / NQ));
        scan_rec_k<<<1, 128>>>(gamma_w, gamma_b, q * (BB / NQ));
        scale_att_k<<<SL_Q, 256>>>(x, Wa_w, Wa_b, out, q * SL_Q);
    }
}

// round 12
// speedup vs baseline: 1.5864x; 1.5864x over previous
#include <cuda_runtime.h>

#define NT   128    // B*T
#define BB   16
#define TT   8
#define CC   512
#define C8   64
#define HW4  196    // 784/4

// Scratch (no device allocation -> __device__ globals)
__device__ float g_xv[NT * CC];
__device__ float g_left[NT * C8];
__device__ float g_right[NT * C8];
__device__ float g_state[NT * C8];

// ---------------------------------------------------------------------------
// Kernel 1: spatial mean pool. 4 rows/block, 64 threads/row, float4 I/O.
// Ascending block order: at completion, L2 holds the TAIL of x.
// ---------------------------------------------------------------------------
__global__ void pool_k(const float* __restrict__ x) {
    __shared__ float s_part[4][2];
    int tid = threadIdx.x;
    int sub = tid >> 6, i = tid & 63;
    int row = blockIdx.x * 4 + sub;
    const float4* xi = reinterpret_cast<const float4*>(x) + (size_t)row * HW4;

    float4 v0 = xi[i];
    float4 v1 = xi[i + 64];
    float4 v2 = xi[i + 128];
    float s = 0.f;
    if (i < 4) { float4 tv = xi[i + 192]; s = (tv.x + tv.y) + (tv.z + tv.w); }
    s += (v0.x + v0.y) + (v0.z + v0.w);
    s += (v1.x + v1.y) + (v1.z + v1.w);
    s += (v2.x + v2.y) + (v2.z + v2.w);

    #pragma unroll
    for (int o = 16; o; o >>= 1) s += __shfl_xor_sync(0xffffffffu, s, o);
    if ((i & 31) == 0) s_part[sub][i >> 5] = s;
    __syncthreads();
    if (i == 0)
        g_xv[row] = (s_part[sub][0] + s_part[sub][1]) * (1.0f / 784.0f);
}

// ---------------------------------------------------------------------------
// Kernel 2: left = relu(BN(xv @ w1^T)), right = relu(BN(xv @ w2^T)).
// ---------------------------------------------------------------------------
__global__ void gemm_bn_k(const float* __restrict__ w1,
                          const float* __restrict__ bn1g, const float* __restrict__ bn1b,
                          const float* __restrict__ bn1m, const float* __restrict__ bn1v,
                          const float* __restrict__ w2,
                          const float* __restrict__ bn2g, const float* __restrict__ bn2b,
                          const float* __restrict__ bn2m, const float* __restrict__ bn2v) {
    __shared__ float sx[CC];
    int nt  = blockIdx.x;
    int tid = threadIdx.x;
    #pragma unroll
    for (int i = tid; i < CC; i += 128) sx[i] = g_xv[nt * CC + i];
    __syncthreads();

    int ch = tid & 63;
    const float* wsel = (tid < 64) ? w1   : w2;
    const float* gsel = (tid < 64) ? bn1g : bn2g;
    const float* bsel = (tid < 64) ? bn1b : bn2b;
    const float* msel = (tid < 64) ? bn1m : bn2m;
    const float* vsel = (tid < 64) ? bn1v : bn2v;

    const float4* wr4 = reinterpret_cast<const float4*>(wsel + ch * CC);
    const float4* sx4 = reinterpret_cast<const float4*>(sx);
    float a0 = 0.f, a1 = 0.f, a2 = 0.f, a3 = 0.f;
    #pragma unroll 8
    for (int k = 0; k < CC / 4; k++) {
        float4 wv = __ldg(wr4 + k);
        float4 xv = sx4[k];
        a0 += xv.x * wv.x;
        a1 += xv.y * wv.y;
        a2 += xv.z * wv.z;
        a3 += xv.w * wv.w;
    }
    float acc   = (a0 + a1) + (a2 + a3);
    float scale = gsel[ch] * rsqrtf(vsel[ch] + 1e-5f);
    float val   = fmaxf((acc - msel[ch]) * scale + bsel[ch], 0.f);
    if (tid < 64) g_left[nt * C8 + ch]  = val;
    else          g_right[nt * C8 + ch] = val;
}

// ---------------------------------------------------------------------------
// Kernel 3: register-resident gated scan. One block, 16 warps (warp = batch).
// ---------------------------------------------------------------------------
__global__ void scan_rec_k(const float* __restrict__ gamma_w,
                           const float* __restrict__ gamma_b) {
    int b    = threadIdx.x >> 5;          // 16 warps = 16 batches
    int lane = threadIdx.x & 31;

    float L0[7], L1[7], R0[7], R1[7];
    #pragma unroll
    for (int t = 0; t < 7; t++) {
        L0[t] = g_left [(b * TT + t)     * C8 + lane];
        L1[t] = g_left [(b * TT + t)     * C8 + lane + 32];
        R0[t] = g_right[(b * TT + t + 1) * C8 + lane];
        R1[t] = g_right[(b * TT + t + 1) * C8 + lane + 32];
    }
    float gm0 = __ldg(gamma_w + lane);
    float gm1 = __ldg(gamma_w + lane + 32);
    float gm2 = __ldg(gamma_w + lane + 64);
    float gm3 = __ldg(gamma_w + lane + 96);
    float gb  = __ldg(gamma_b);

    float s0 = 1.f, s1 = 1.f;             // initial state = padded ones
    #pragma unroll
    for (int t = 0; t < TT; t++) {
        float d0 = (t < TT - 1) ? (L0[t] - R0[t]) : 1.f;
        float d1 = (t < TT - 1) ? (L1[t] - R1[t]) : 1.f;
        float acc = d0 * gm0 + d1 * gm1 + s0 * gm2 + s1 * gm3;
        #pragma unroll
        for (int o = 16; o; o >>= 1) acc += __shfl_xor_sync(0xffffffffu, acc, o);
        float g = 1.0f / (1.0f + __expf(-(acc + gb)));
        s0 = d0 * g + s0 * (1.0f - g);
        s1 = d1 * g + s1 * (1.0f - g);
        g_state[(b * TT + t) * C8 + lane]      = s0;
        g_state[(b * TT + t) * C8 + lane + 32] = s1;
    }
}

// ---------------------------------------------------------------------------
// Kernel 4: fused attention + scale. REVERSED block order: first blocks read
// the tail of x, which pool just left resident in L2. Out stores are
// WRITE-THROUGH (__stwt): no dirty out lines in L2 -> x residency preserved,
// and no writeback burst at the next replay's pool start.
// ---------------------------------------------------------------------------
__global__ void scale_att_k(const float* __restrict__ x,
                            const float* __restrict__ Wa_w,
                            const float* __restrict__ Wa_b,
                            float* __restrict__ out) {
    __shared__ float s_part[4][2];
    int tid  = threadIdx.x;
    int sub  = tid >> 6, i = tid & 63;
    int rb   = gridDim.x - 1 - blockIdx.x;   // reversed
    int row  = rb * 4 + sub;                 // (nt*CC + c) row id
    int nt   = row >> 9;
    int c    = row & (CC - 1);

    const float4* xi = reinterpret_cast<const float4*>(x)   + (size_t)row * HW4;
    float4*       xo = reinterpret_cast<float4*>(out)       + (size_t)row * HW4;

    // issue bulk loads first (long-latency, overlap with sig computation)
    float4 v0 = __ldg(xi + i);
    float4 v1 = __ldg(xi + i + 64);
    float4 v2 = __ldg(xi + i + 128);
    float4 v3;
    bool tail = (i < 4);
    if (tail) v3 = __ldg(xi + i + 192);

    // inline attention dot: state[nt][i] * Wa[c][i], 64 threads, 1 elem each
    float p = g_state[nt * C8 + i] * __ldg(Wa_w + c * C8 + i);
    #pragma unroll
    for (int o = 16; o; o >>= 1) p += __shfl_xor_sync(0xffffffffu, p, o);
    if ((i & 31) == 0) s_part[sub][i >> 5] = p;
    __syncthreads();
    float a = s_part[sub][0] + s_part[sub][1] + __ldg(Wa_b + c);
    float s = 1.0f / (1.0f + __expf(-a));

    v0.x *= s; v0.y *= s; v0.z *= s; v0.w *= s;
    v1.x *= s; v1.y *= s; v1.z *= s; v1.w *= s;
    v2.x *= s; v2.y *= s; v2.z *= s; v2.w *= s;
    __stwt(xo + i,       v0);
    __stwt(xo + i + 64,  v1);
    __stwt(xo + i + 128, v2);
    if (tail) {
        v3.x *= s; v3.y *= s; v3.z *= s; v3.w *= s;
        __stwt(xo + i + 192, v3);
    }
}

// ---------------------------------------------------------------------------
extern "C" void kernel_launch(void* const* d_in, const int* in_sizes, int n_in,
                              void* d_out, int out_size) {
    const float* x       = (const float*)d_in[0];
    const float* w1      = (const float*)d_in[1];
    const float* bn1_g   = (const float*)d_in[2];
    const float* bn1_b   = (const float*)d_in[3];
    const float* bn1_m   = (const float*)d_in[4];
    const float* bn1_v   = (const float*)d_in[5];
    const float* w2      = (const float*)d_in[6];
    const float* bn2_g   = (const float*)d_in[7];
    const float* bn2_b   = (const float*)d_in[8];
    const float* bn2_m   = (const float*)d_in[9];
    const float* bn2_v   = (const float*)d_in[10];
    const float* Wa_w    = (const float*)d_in[11];
    const float* Wa_b    = (const float*)d_in[12];
    const float* gamma_w = (const float*)d_in[13];
    const float* gamma_b = (const float*)d_in[14];
    float* out = (float*)d_out;

    pool_k<<<(NT * CC) / 4, 256>>>(x);                       // 16384 blocks
    gemm_bn_k<<<NT, 128>>>(w1, bn1_g, bn1_b, bn1_m, bn1_v,
                           w2, bn2_g, bn2_b, bn2_m, bn2_v);
    scan_rec_k<<<1, 512>>>(gamma_w, gamma_b);                // 1 block, registers
    scale_att_k<<<(NT * CC) / 4, 256>>>(x, Wa_w, Wa_b, out); // 16384 blocks
}

// round 13
// speedup vs baseline: 1.6248x; 1.0242x over previous
#include <cuda_runtime.h>

#define NT   128    // B*T
#define BB   16
#define TT   8
#define CC   512
#define C8   64
#define HW4  196    // 784/4

// Scratch (no device allocation -> __device__ globals; zero-initialized)
__device__ float g_xv[NT * CC];
__device__ float g_left[NT * C8];
__device__ float g_right[NT * C8];
__device__ float g_state[NT * C8];
__device__ int   g_cnt_b[BB];      // self-resetting last-finisher counters

// ---------------------------------------------------------------------------
// Kernel 1: spatial mean pool. 4 rows/block, 64 threads/row, float4 I/O.
// Ascending block order: at completion, L2 holds the TAIL of x.
// ---------------------------------------------------------------------------
__global__ void pool_k(const float* __restrict__ x) {
    __shared__ float s_part[4][2];
    int tid = threadIdx.x;
    int sub = tid >> 6, i = tid & 63;
    int row = blockIdx.x * 4 + sub;
    const float4* xi = reinterpret_cast<const float4*>(x) + (size_t)row * HW4;

    float4 v0 = xi[i];
    float4 v1 = xi[i + 64];
    float4 v2 = xi[i + 128];
    float s = 0.f;
    if (i < 4) { float4 tv = xi[i + 192]; s = (tv.x + tv.y) + (tv.z + tv.w); }
    s += (v0.x + v0.y) + (v0.z + v0.w);
    s += (v1.x + v1.y) + (v1.z + v1.w);
    s += (v2.x + v2.y) + (v2.z + v2.w);

    #pragma unroll
    for (int o = 16; o; o >>= 1) s += __shfl_xor_sync(0xffffffffu, s, o);
    if ((i & 31) == 0) s_part[sub][i >> 5] = s;
    __syncthreads();
    if (i == 0)
        g_xv[row] = (s_part[sub][0] + s_part[sub][1]) * (1.0f / 784.0f);
}

// ---------------------------------------------------------------------------
// Kernel 2 (merged): gemm+BN+ReLU (128 blocks, one nt each — proven body)
// + per-batch last-finisher scan. Only 128 fences/atomics grid-wide: the 8th
// block to finish a batch's nts runs that batch's 8-step register scan on
// its warp 0. Counters self-reset -> graph-replay deterministic.
// ---------------------------------------------------------------------------
__global__ void gemm_scan_k(const float* __restrict__ w1,
                            const float* __restrict__ bn1g, const float* __restrict__ bn1b,
                            const float* __restrict__ bn1m, const float* __restrict__ bn1v,
                            const float* __restrict__ w2,
                            const float* __restrict__ bn2g, const float* __restrict__ bn2b,
                            const float* __restrict__ bn2m, const float* __restrict__ bn2v,
                            const float* __restrict__ gamma_w,
                            const float* __restrict__ gamma_b) {
    __shared__ float sx[CC];
    __shared__ int   s_b;
    int nt  = blockIdx.x;
    int tid = threadIdx.x;
    #pragma unroll
    for (int i = tid; i < CC; i += 128) sx[i] = g_xv[nt * CC + i];
    __syncthreads();

    int ch = tid & 63;
    const float* wsel = (tid < 64) ? w1   : w2;
    const float* gsel = (tid < 64) ? bn1g : bn2g;
    const float* bsel = (tid < 64) ? bn1b : bn2b;
    const float* msel = (tid < 64) ? bn1m : bn2m;
    const float* vsel = (tid < 64) ? bn1v : bn2v;

    const float4* wr4 = reinterpret_cast<const float4*>(wsel + ch * CC);
    const float4* sx4 = reinterpret_cast<const float4*>(sx);
    float a0 = 0.f, a1 = 0.f, a2 = 0.f, a3 = 0.f;
    #pragma unroll 8
    for (int k = 0; k < CC / 4; k++) {
        float4 wv = __ldg(wr4 + k);
        float4 xv = sx4[k];
        a0 += xv.x * wv.x;
        a1 += xv.y * wv.y;
        a2 += xv.z * wv.z;
        a3 += xv.w * wv.w;
    }
    float acc   = (a0 + a1) + (a2 + a3);
    float scale = gsel[ch] * rsqrtf(vsel[ch] + 1e-5f);
    float val   = fmaxf((acc - msel[ch]) * scale + bsel[ch], 0.f);
    if (tid < 64) g_left[nt * C8 + ch]  = val;
    else          g_right[nt * C8 + ch] = val;

    // ---- per-batch last-finisher: run the scan ----
    __threadfence();                        // release left/right (128 blocks only)
    __syncthreads();
    int b = nt >> 3;
    if (tid == 0) {
        int old = atomicAdd(&g_cnt_b[b], 1);
        if (old == TT - 1) { g_cnt_b[b] = 0; s_b = b; } else s_b = -1;
    }
    __syncthreads();
    if (s_b < 0 || tid >= 32) return;

    __threadfence();                        // acquire left/right
    int bb = s_b, lane = tid;
    float L0[7], L1[7], R0[7], R1[7];
    #pragma unroll
    for (int t = 0; t < 7; t++) {
        L0[t] = g_left [(bb * TT + t)     * C8 + lane];
        L1[t] = g_left [(bb * TT + t)     * C8 + lane + 32];
        R0[t] = g_right[(bb * TT + t + 1) * C8 + lane];
        R1[t] = g_right[(bb * TT + t + 1) * C8 + lane + 32];
    }
    float gm0 = __ldg(gamma_w + lane);
    float gm1 = __ldg(gamma_w + lane + 32);
    float gm2 = __ldg(gamma_w + lane + 64);
    float gm3 = __ldg(gamma_w + lane + 96);
    float gb  = __ldg(gamma_b);

    float s0 = 1.f, s1 = 1.f;
    #pragma unroll
    for (int t = 0; t < TT; t++) {
        float d0 = (t < TT - 1) ? (L0[t] - R0[t]) : 1.f;
        float d1 = (t < TT - 1) ? (L1[t] - R1[t]) : 1.f;
        float a = d0 * gm0 + d1 * gm1 + s0 * gm2 + s1 * gm3;
        #pragma unroll
        for (int o = 16; o; o >>= 1) a += __shfl_xor_sync(0xffffffffu, a, o);
        float g = 1.0f / (1.0f + __expf(-(a + gb)));
        s0 = d0 * g + s0 * (1.0f - g);
        s1 = d1 * g + s1 * (1.0f - g);
        g_state[(bb * TT + t) * C8 + lane]      = s0;
        g_state[(bb * TT + t) * C8 + lane + 32] = s1;
    }
}

// ---------------------------------------------------------------------------
// Kernel 3: fused attention + scale. REVERSED block order (L2 reuse of the
// x tail pool left resident) + __stcs streaming stores (proven best combo).
// ---------------------------------------------------------------------------
__global__ void scale_att_k(const float* __restrict__ x,
                            const float* __restrict__ Wa_w,
                            const float* __restrict__ Wa_b,
                            float* __restrict__ out) {
    __shared__ float s_part[4][2];
    int tid  = threadIdx.x;
    int sub  = tid >> 6, i = tid & 63;
    int rb   = gridDim.x - 1 - blockIdx.x;   // reversed
    int row  = rb * 4 + sub;                 // (nt*CC + c) row id
    int nt   = row >> 9;
    int c    = row & (CC - 1);

    const float4* xi = reinterpret_cast<const float4*>(x)   + (size_t)row * HW4;
    float4*       xo = reinterpret_cast<float4*>(out)       + (size_t)row * HW4;

    float4 v0 = __ldg(xi + i);
    float4 v1 = __ldg(xi + i + 64);
    float4 v2 = __ldg(xi + i + 128);
    float4 v3;
    bool tail = (i < 4);
    if (tail) v3 = __ldg(xi + i + 192);

    float p = g_state[nt * C8 + i] * __ldg(Wa_w + c * C8 + i);
    #pragma unroll
    for (int o = 16; o; o >>= 1) p += __shfl_xor_sync(0xffffffffu, p, o);
    if ((i & 31) == 0) s_part[sub][i >> 5] = p;
    __syncthreads();
    float a = s_part[sub][0] + s_part[sub][1] + __ldg(Wa_b + c);
    float s = 1.0f / (1.0f + __expf(-a));

    v0.x *= s; v0.y *= s; v0.z *= s; v0.w *= s;
    v1.x *= s; v1.y *= s; v1.z *= s; v1.w *= s;
    v2.x *= s; v2.y *= s; v2.z *= s; v2.w *= s;
    __stcs(xo + i,       v0);
    __stcs(xo + i + 64,  v1);
    __stcs(xo + i + 128, v2);
    if (tail) {
        v3.x *= s; v3.y *= s; v3.z *= s; v3.w *= s;
        __stcs(xo + i + 192, v3);
    }
}

// ---------------------------------------------------------------------------
extern "C" void kernel_launch(void* const* d_in, const int* in_sizes, int n_in,
                              void* d_out, int out_size) {
    const float* x       = (const float*)d_in[0];
    const float* w1      = (const float*)d_in[1];
    const float* bn1_g   = (const float*)d_in[2];
    const float* bn1_b   = (const float*)d_in[3];
    const float* bn1_m   = (const float*)d_in[4];
    const float* bn1_v   = (const float*)d_in[5];
    const float* w2      = (const float*)d_in[6];
    const float* bn2_g   = (const float*)d_in[7];
    const float* bn2_b   = (const float*)d_in[8];
    const float* bn2_m   = (const float*)d_in[9];
    const float* bn2_v   = (const float*)d_in[10];
    const float* Wa_w    = (const float*)d_in[11];
    const float* Wa_b    = (const float*)d_in[12];
    const float* gamma_w = (const float*)d_in[13];
    const float* gamma_b = (const float*)d_in[14];
    float* out = (float*)d_out;

    pool_k<<<(NT * CC) / 4, 256>>>(x);                       // 16384 blocks
    gemm_scan_k<<<NT, 128>>>(w1, bn1_g, bn1_b, bn1_m, bn1_v,
                             w2, bn2_g, bn2_b, bn2_m, bn2_v,
                             gamma_w, gamma_b);              // 128 blocks
    scale_att_k<<<(NT * CC) / 4, 256>>>(x, Wa_w, Wa_b, out); // 16384 blocks
}

// round 14
// speedup vs baseline: 1.6252x; 1.0003x over previous
#include <cuda_runtime.h>

#define NT   128    // B*T
#define BB   16
#define TT   8
#define CC   512
#define C8   64
#define HW4  196    // 784/4

// Scratch (no device allocation -> __device__ globals; zero-initialized)
__device__ float g_xv[NT * CC];
__device__ float g_left[NT * C8];
__device__ float g_right[NT * C8];
__device__ float g_state[NT * C8];
__device__ int   g_cnt_b[BB];      // self-resetting last-finisher counters

// ---------------------------------------------------------------------------
// Kernel 1: spatial mean pool. 4 rows/block, 64 threads/row, float4 I/O.
// Triggers the PDL latch after its store so gemm_scan_k launches early.
// ---------------------------------------------------------------------------
__global__ void pool_k(const float* __restrict__ x) {
    __shared__ float s_part[4][2];
    int tid = threadIdx.x;
    int sub = tid >> 6, i = tid & 63;
    int row = blockIdx.x * 4 + sub;
    const float4* xi = reinterpret_cast<const float4*>(x) + (size_t)row * HW4;

    float4 v0 = xi[i];
    float4 v1 = xi[i + 64];
    float4 v2 = xi[i + 128];
    float s = 0.f;
    if (i < 4) { float4 tv = xi[i + 192]; s = (tv.x + tv.y) + (tv.z + tv.w); }
    s += (v0.x + v0.y) + (v0.z + v0.w);
    s += (v1.x + v1.y) + (v1.z + v1.w);
    s += (v2.x + v2.y) + (v2.z + v2.w);

    #pragma unroll
    for (int o = 16; o; o >>= 1) s += __shfl_xor_sync(0xffffffffu, s, o);
    if ((i & 31) == 0) s_part[sub][i >> 5] = s;
    __syncthreads();
    if (i == 0)
        g_xv[row] = (s_part[sub][0] + s_part[sub][1]) * (1.0f / 784.0f);

    cudaTriggerProgrammaticLaunchCompletion();
}

// ---------------------------------------------------------------------------
// Kernel 2 (merged, PDL secondary): gemm+BN+ReLU (128 blocks, one nt each)
// + per-batch last-finisher scan. Launches during pool's tail; grid-syncs
// before reading g_xv. Triggers the next PDL latch right after the gemm
// stores so scale_att_k overlaps the scan epilogue.
// ---------------------------------------------------------------------------
__global__ void gemm_scan_k(const float* __restrict__ w1,
                            const float* __restrict__ bn1g, const float* __restrict__ bn1b,
                            const float* __restrict__ bn1m, const float* __restrict__ bn1v,
                            const float* __restrict__ w2,
                            const float* __restrict__ bn2g, const float* __restrict__ bn2b,
                            const float* __restrict__ bn2m, const float* __restrict__ bn2v,
                            const float* __restrict__ gamma_w,
                            const float* __restrict__ gamma_b) {
    __shared__ float sx[CC];
    __shared__ int   s_b;
    int nt  = blockIdx.x;
    int tid = threadIdx.x;

    cudaGridDependencySynchronize();        // wait for pool's g_xv

    #pragma unroll
    for (int i = tid; i < CC; i += 128) sx[i] = g_xv[nt * CC + i];
    __syncthreads();

    int ch = tid & 63;
    const float* wsel = (tid < 64) ? w1   : w2;
    const float* gsel = (tid < 64) ? bn1g : bn2g;
    const float* bsel = (tid < 64) ? bn1b : bn2b;
    const float* msel = (tid < 64) ? bn1m : bn2m;
    const float* vsel = (tid < 64) ? bn1v : bn2v;

    const float4* wr4 = reinterpret_cast<const float4*>(wsel + ch * CC);
    const float4* sx4 = reinterpret_cast<const float4*>(sx);
    float a0 = 0.f, a1 = 0.f, a2 = 0.f, a3 = 0.f;
    #pragma unroll 8
    for (int k = 0; k < CC / 4; k++) {
        float4 wv = __ldg(wr4 + k);
        float4 xv = sx4[k];
        a0 += xv.x * wv.x;
        a1 += xv.y * wv.y;
        a2 += xv.z * wv.z;
        a3 += xv.w * wv.w;
    }
    float acc   = (a0 + a1) + (a2 + a3);
    float scale = gsel[ch] * rsqrtf(vsel[ch] + 1e-5f);
    float val   = fmaxf((acc - msel[ch]) * scale + bsel[ch], 0.f);
    if (tid < 64) g_left[nt * C8 + ch]  = val;
    else          g_right[nt * C8 + ch] = val;

    cudaTriggerProgrammaticLaunchCompletion();   // let scale_att launch early

    // ---- per-batch last-finisher: run the scan ----
    __threadfence();                        // release left/right (128 blocks only)
    __syncthreads();
    int b = nt >> 3;
    if (tid == 0) {
        int old = atomicAdd(&g_cnt_b[b], 1);
        if (old == TT - 1) { g_cnt_b[b] = 0; s_b = b; } else s_b = -1;
    }
    __syncthreads();
    if (s_b < 0 || tid >= 32) return;

    __threadfence();                        // acquire left/right
    int bb = s_b, lane = tid;
    float L0[7], L1[7], R0[7], R1[7];
    #pragma unroll
    for (int t = 0; t < 7; t++) {
        L0[t] = g_left [(bb * TT + t)     * C8 + lane];
        L1[t] = g_left [(bb * TT + t)     * C8 + lane + 32];
        R0[t] = g_right[(bb * TT + t + 1) * C8 + lane];
        R1[t] = g_right[(bb * TT + t + 1) * C8 + lane + 32];
    }
    float gm0 = __ldg(gamma_w + lane);
    float gm1 = __ldg(gamma_w + lane + 32);
    float gm2 = __ldg(gamma_w + lane + 64);
    float gm3 = __ldg(gamma_w + lane + 96);
    float gb  = __ldg(gamma_b);

    float s0 = 1.f, s1 = 1.f;
    #pragma unroll
    for (int t = 0; t < TT; t++) {
        float d0 = (t < TT - 1) ? (L0[t] - R0[t]) : 1.f;
        float d1 = (t < TT - 1) ? (L1[t] - R1[t]) : 1.f;
        float a = d0 * gm0 + d1 * gm1 + s0 * gm2 + s1 * gm3;
        #pragma unroll
        for (int o = 16; o; o >>= 1) a += __shfl_xor_sync(0xffffffffu, a, o);
        float g = 1.0f / (1.0f + __expf(-(a + gb)));
        s0 = d0 * g + s0 * (1.0f - g);
        s1 = d1 * g + s1 * (1.0f - g);
        g_state[(bb * TT + t) * C8 + lane]      = s0;
        g_state[(bb * TT + t) * C8 + lane + 32] = s1;
    }
}

// ---------------------------------------------------------------------------
// Kernel 3 (PDL secondary): fused attention + scale, REVERSED block order.
// Issues its x loads + Wa load BEFORE the grid-dependency sync so wave-1
// load latency overlaps gemm_scan's epilogue; reads g_state only after sync.
// ---------------------------------------------------------------------------
__global__ void scale_att_k(const float* __restrict__ x,
                            const float* __restrict__ Wa_w,
                            const float* __restrict__ Wa_b,
                            float* __restrict__ out) {
    __shared__ float s_part[4][2];
    int tid  = threadIdx.x;
    int sub  = tid >> 6, i = tid & 63;
    int rb   = gridDim.x - 1 - blockIdx.x;   // reversed
    int row  = rb * 4 + sub;                 // (nt*CC + c) row id
    int nt   = row >> 9;
    int c    = row & (CC - 1);

    const float4* xi = reinterpret_cast<const float4*>(x)   + (size_t)row * HW4;
    float4*       xo = reinterpret_cast<float4*>(out)       + (size_t)row * HW4;

    // independent loads first — overlap with the producer kernel's tail
    float4 v0 = __ldg(xi + i);
    float4 v1 = __ldg(xi + i + 64);
    float4 v2 = __ldg(xi + i + 128);
    float4 v3;
    bool tail = (i < 4);
    if (tail) v3 = __ldg(xi + i + 192);
    float wa = __ldg(Wa_w + c * C8 + i);
    float wb = __ldg(Wa_b + c);

    cudaGridDependencySynchronize();         // wait for g_state

    float p = g_state[nt * C8 + i] * wa;
    #pragma unroll
    for (int o = 16; o; o >>= 1) p += __shfl_xor_sync(0xffffffffu, p, o);
    if ((i & 31) == 0) s_part[sub][i >> 5] = p;
    __syncthreads();
    float a = s_part[sub][0] + s_part[sub][1] + wb;
    float s = 1.0f / (1.0f + __expf(-a));

    v0.x *= s; v0.y *= s; v0.z *= s; v0.w *= s;
    v1.x *= s; v1.y *= s; v1.z *= s; v1.w *= s;
    v2.x *= s; v2.y *= s; v2.z *= s; v2.w *= s;
    __stcs(xo + i,       v0);
    __stcs(xo + i + 64,  v1);
    __stcs(xo + i + 128, v2);
    if (tail) {
        v3.x *= s; v3.y *= s; v3.z *= s; v3.w *= s;
        __stcs(xo + i + 192, v3);
    }
}

// ---------------------------------------------------------------------------
extern "C" void kernel_launch(void* const* d_in, const int* in_sizes, int n_in,
                              void* d_out, int out_size) {
    const float* x       = (const float*)d_in[0];
    const float* w1      = (const float*)d_in[1];
    const float* bn1_g   = (const float*)d_in[2];
    const float* bn1_b   = (const float*)d_in[3];
    const float* bn1_m   = (const float*)d_in[4];
    const float* bn1_v   = (const float*)d_in[5];
    const float* w2      = (const float*)d_in[6];
    const float* bn2_g   = (const float*)d_in[7];
    const float* bn2_b   = (const float*)d_in[8];
    const float* bn2_m   = (const float*)d_in[9];
    const float* bn2_v   = (const float*)d_in[10];
    const float* Wa_w    = (const float*)d_in[11];
    const float* Wa_b    = (const float*)d_in[12];
    const float* gamma_w = (const float*)d_in[13];
    const float* gamma_b = (const float*)d_in[14];
    float* out = (float*)d_out;

    pool_k<<<(NT * CC) / 4, 256>>>(x);                       // 16384 blocks

    cudaLaunchAttribute attr[1];
    attr[0].id = cudaLaunchAttributeProgrammaticStreamSerialization;
    attr[0].val.programmaticStreamSerializationAllowed = 1;

    {   // gemm_scan_k as PDL secondary of pool_k
        cudaLaunchConfig_t cfg = {};
        cfg.gridDim  = dim3(NT, 1, 1);
        cfg.blockDim = dim3(128, 1, 1);
        cfg.attrs    = attr;
        cfg.numAttrs = 1;
        cudaLaunchKernelEx(&cfg, gemm_scan_k,
                           w1, bn1_g, bn1_b, bn1_m, bn1_v,
                           w2, bn2_g, bn2_b, bn2_m, bn2_v,
                           gamma_w, gamma_b);
    }
    {   // scale_att_k as PDL secondary of gemm_scan_k
        cudaLaunchConfig_t cfg = {};
        cfg.gridDim  = dim3((NT * CC) / 4, 1, 1);
        cfg.blockDim = dim3(256, 1, 1);
        cfg.attrs    = attr;
        cfg.numAttrs = 1;
        cudaLaunchKernelEx(&cfg, scale_att_k, x, Wa_w, Wa_b, out);
    }
}